// round 1
// baseline (speedup 1.0000x reference)
#include <cuda_runtime.h>
#include <cstdint>
#include <math.h>

#define T_ 5
#define H_ 64
#define W_ 96
#define HW_ (H_ * W_)
#define CIN_ 256
#define HEADS_ 8
#define LVLS_ 5
#define PTS_ 4

// ---------------- scratch (static device globals; no allocation) ----------------
__device__ float g_value[(size_t)T_ * HEADS_ * HW_ * 32];   // [t][head][y][x][dh]
__device__ float g_off  [(size_t)T_ * 320 * HW_];           // [t][c][y][x]
__device__ float g_attn [(size_t)T_ * 160 * HW_];           // [t][c][y][x]
__device__ float g_adds [(size_t)4 * 5 * 2 * HW_];          // [i(0..3)][j][c][y][x]
__device__ float g_samp [(size_t)T_ * 256 * HW_];           // [t][c][y][x]

// ---------------- direct 3x3 conv, pad=1, stride=1 ----------------
// Block: 128 threads. Tile: 16 rows x 32 cols of pixels, 8 output channels.
// Each thread: 1 row x 4 cols x 8 co = 32 accumulators.
// LAYOUT 0: out[((t*Cout+co)*H + y)*W + x]
// LAYOUT 1: g_value[(((t*8+head)*HW + y*W + x) << 5) + dh], co = head*32+dh
template <int LAYOUT>
__global__ void __launch_bounds__(128) conv3x3_kernel(
    const float* __restrict__ in, const float* __restrict__ wgt,
    const float* __restrict__ bias, float* __restrict__ out, int Cout)
{
    const int co_blocks = Cout >> 3;
    const int t   = blockIdx.z / co_blocks;
    const int co0 = (blockIdx.z % co_blocks) << 3;
    const int gy0 = blockIdx.y << 4;
    const int gx0 = blockIdx.x << 5;
    const int tid = threadIdx.x;
    const int ty  = tid >> 3;          // 0..15
    const int tx  = (tid & 7) << 2;    // 0,4,...,28

    __shared__ float s_in[18 * 34];
    __shared__ float s_w[72];

    const float* in_t = in + (size_t)t * CIN_ * HW_;

    float acc[8][4];
#pragma unroll
    for (int k = 0; k < 8; k++)
#pragma unroll
        for (int p = 0; p < 4; p++) acc[k][p] = 0.f;

    for (int ci = 0; ci < CIN_; ci++) {
        const float* img = in_t + (size_t)ci * HW_;
        for (int i = tid; i < 18 * 34; i += 128) {
            int r = i / 34, c = i - r * 34;
            int gy = gy0 - 1 + r, gx = gx0 - 1 + c;
            float v = 0.f;
            if ((unsigned)gy < H_ && (unsigned)gx < W_) v = img[gy * W_ + gx];
            s_in[i] = v;
        }
        if (tid < 72) {
            int k = tid / 9, e = tid - k * 9;
            s_w[tid] = wgt[((size_t)(co0 + k) * CIN_ + ci) * 9 + e];
        }
        __syncthreads();

        float xv[18];
#pragma unroll
        for (int r = 0; r < 3; r++)
#pragma unroll
            for (int c = 0; c < 6; c++)
                xv[r * 6 + c] = s_in[(ty + r) * 34 + tx + c];

#pragma unroll
        for (int k = 0; k < 8; k++) {
            float w0 = s_w[k*9+0], w1 = s_w[k*9+1], w2 = s_w[k*9+2];
            float w3 = s_w[k*9+3], w4 = s_w[k*9+4], w5 = s_w[k*9+5];
            float w6 = s_w[k*9+6], w7 = s_w[k*9+7], w8 = s_w[k*9+8];
#pragma unroll
            for (int p = 0; p < 4; p++) {
                float a = acc[k][p];
                a = fmaf(w0, xv[p + 0],  a);
                a = fmaf(w1, xv[p + 1],  a);
                a = fmaf(w2, xv[p + 2],  a);
                a = fmaf(w3, xv[p + 6],  a);
                a = fmaf(w4, xv[p + 7],  a);
                a = fmaf(w5, xv[p + 8],  a);
                a = fmaf(w6, xv[p + 12], a);
                a = fmaf(w7, xv[p + 13], a);
                a = fmaf(w8, xv[p + 14], a);
                acc[k][p] = a;
            }
        }
        __syncthreads();
    }

    const int gy = gy0 + ty;
#pragma unroll
    for (int k = 0; k < 8; k++) {
        const int co = co0 + k;
        const float b = bias[co];
#pragma unroll
        for (int p = 0; p < 4; p++) {
            const int gx = gx0 + tx + p;
            const float v = acc[k][p] + b;
            if (LAYOUT == 0) {
                out[((size_t)(t * Cout + co) * H_ + gy) * W_ + gx] = v;
            } else {
                const int head = co >> 5, dh = co & 31;
                g_value[(((size_t)(t * 8 + head) * HW_ + gy * W_ + gx) << 5) + dh] = v;
            }
        }
    }
}

// ---------------- flow composition ----------------
__global__ void flow_init_kernel(const float* __restrict__ ff, const float* __restrict__ fb)
{
    int p = blockIdx.x * blockDim.x + threadIdx.x;
    if (p >= HW_) return;
#pragma unroll
    for (int i = 0; i < 4; i++)
#pragma unroll
        for (int j = 0; j < 5; j++) {
            g_adds[((i * 5 + j) * 2 + 0) * HW_ + p] = 0.f;
            g_adds[((i * 5 + j) * 2 + 1) * HW_ + p] = 0.f;
        }
#pragma unroll
    for (int k = 0; k < 4; k++) {  // forward: adds(k, k+1) = ff[k]
        g_adds[((k * 5 + (k + 1)) * 2 + 0) * HW_ + p] = ff[(k * 2 + 0) * HW_ + p];
        g_adds[((k * 5 + (k + 1)) * 2 + 1) * HW_ + p] = ff[(k * 2 + 1) * HW_ + p];
    }
#pragma unroll
    for (int k = 0; k < 3; k++) {  // backward: adds(k+1, k) = fb[k]
        g_adds[(((k + 1) * 5 + k) * 2 + 0) * HW_ + p] = fb[(k * 2 + 0) * HW_ + p];
        g_adds[(((k + 1) * 5 + k) * 2 + 1) * HW_ + p] = fb[(k * 2 + 1) * HW_ + p];
    }
}

// dst = base + bilinear_zero_sample(tgt, grid + base)
__global__ void flow_warp_kernel(int base_off, int tgt_off, int dst_off)
{
    int p = blockIdx.x * blockDim.x + threadIdx.x;
    if (p >= HW_) return;
    int y = p / W_, x = p - y * W_;
    const float* base = g_adds + base_off;
    const float* tgt  = g_adds + tgt_off;
    float fx = base[p], fy = base[HW_ + p];
    float px = (float)x + fx, py = (float)y + fy;
    float x0f = floorf(px), y0f = floorf(py);
    int   x0 = (int)x0f, y0 = (int)y0f;
    float wx1 = px - x0f, wx0 = 1.f - wx1;
    float wy1 = py - y0f, wy0 = 1.f - wy1;
    float s0 = 0.f, s1 = 0.f;
    const int xs[4] = {x0, x0 + 1, x0, x0 + 1};
    const int ys[4] = {y0, y0, y0 + 1, y0 + 1};
    const float ws[4] = {wx0 * wy0, wx1 * wy0, wx0 * wy1, wx1 * wy1};
#pragma unroll
    for (int k = 0; k < 4; k++) {
        if ((unsigned)xs[k] < W_ && (unsigned)ys[k] < H_) {
            int idx = ys[k] * W_ + xs[k];
            s0 = fmaf(tgt[idx], ws[k], s0);
            s1 = fmaf(tgt[HW_ + idx], ws[k], s1);
        }
    }
    g_adds[dst_off + p]        = fx + s0;
    g_adds[dst_off + HW_ + p]  = fy + s1;
}

// ---------------- deformable sampling + softmax attention ----------------
// One warp per (query, head). lane = dh channel (32). Taps are lane-coalesced
// 128B loads from the [t][head][y][x][dh] value layout.
__global__ void __launch_bounds__(256) sample_kernel(const float* __restrict__ ref_pts)
{
    const int item = blockIdx.x * 8 + (threadIdx.x >> 5);
    const int lane = threadIdx.x & 31;
    const int head = item & 7;
    const int q    = item >> 3;
    const int t    = q / HW_;
    const int p    = q - t * HW_;
    const int y    = p / W_;
    const int x    = p - y * W_;
    const int ri   = (t == 4) ? 3 : t;   // reference builds row 4 identical to row 3
    (void)y; (void)x;

    // softmax over 20 logits (uniform addresses -> broadcast loads)
    const float* attn_base = g_attn + (size_t)t * 160 * HW_ + (size_t)head * 20 * HW_ + p;
    float lg[20];
    float mx = -1e30f;
#pragma unroll
    for (int i = 0; i < 20; i++) { lg[i] = attn_base[(size_t)i * HW_]; mx = fmaxf(mx, lg[i]); }
    float ssum = 0.f;
#pragma unroll
    for (int i = 0; i < 20; i++) { lg[i] = expf(lg[i] - mx); ssum += lg[i]; }
    const float inv = 1.f / ssum;

    const float* off_base = g_off + (size_t)t * 320 * HW_ + p;
    float out = 0.f;
#pragma unroll
    for (int l = 0; l < LVLS_; l++) {
        const float ax = g_adds[((ri * 5 + l) * 2 + 0) * HW_ + p];
        const float ay = g_adds[((ri * 5 + l) * 2 + 1) * HW_ + p];
        const float rx = ref_pts[((size_t)q * 5 + l) * 2 + 0];
        const float ry = ref_pts[((size_t)q * 5 + l) * 2 + 1];
        const float* vimg = g_value + ((size_t)(l * 8 + head) * HW_ << 5) + lane;
#pragma unroll
        for (int pt = 0; pt < PTS_; pt++) {
            const int ch = ((head * 5 + l) * 4 + pt) * 2;
            const float ox = off_base[(size_t)ch * HW_] + ax;
            const float oy = off_base[(size_t)(ch + 1) * HW_] + ay;
            const float px = fmaf(rx, (float)W_, ox) - 0.5f;
            const float py = fmaf(ry, (float)H_, oy) - 0.5f;
            const float x0f = floorf(px), y0f = floorf(py);
            const int   x0 = (int)x0f, y0 = (int)y0f;
            const float wx1 = px - x0f, wx0 = 1.f - wx1;
            const float wy1 = py - y0f, wy0 = 1.f - wy1;
            float s = 0.f;
            const bool vx0 = (unsigned)x0 < W_,        vx1 = (unsigned)(x0 + 1) < W_;
            const bool vy0 = (unsigned)y0 < H_,        vy1 = (unsigned)(y0 + 1) < H_;
            if (vy0) {
                const long long r0 = (long long)y0 * W_;
                if (vx0) s = fmaf(vimg[(r0 + x0) << 5],     wx0 * wy0, s);
                if (vx1) s = fmaf(vimg[(r0 + x0 + 1) << 5], wx1 * wy0, s);
            }
            if (vy1) {
                const long long r1 = (long long)(y0 + 1) * W_;
                if (vx0) s = fmaf(vimg[(r1 + x0) << 5],     wx0 * wy1, s);
                if (vx1) s = fmaf(vimg[(r1 + x0 + 1) << 5], wx1 * wy1, s);
            }
            out = fmaf(s, lg[l * 4 + pt] * inv, out);
        }
    }
    g_samp[((size_t)t * 256 + (head << 5) + lane) * HW_ + p] = out;
}

// ---------------- launch ----------------
extern "C" void kernel_launch(void* const* d_in, const int* in_sizes, int n_in,
                              void* d_out, int out_size)
{
    (void)in_sizes; (void)n_in; (void)out_size;
    const float* query         = (const float*)d_in[0];
    const float* input_flatten = (const float*)d_in[1];
    const float* ref_pts       = (const float*)d_in[2];
    // d_in[3] spatial shapes, d_in[4] level start, d_in[5] padding mask (all-false): unused
    const float* ff     = (const float*)d_in[6];
    const float* fb     = (const float*)d_in[7];
    const float* w_off  = (const float*)d_in[8];
    const float* b_off  = (const float*)d_in[9];
    const float* w_attn = (const float*)d_in[10];
    const float* b_attn = (const float*)d_in[11];
    const float* w_val  = (const float*)d_in[12];
    const float* b_val  = (const float*)d_in[13];
    const float* w_out  = (const float*)d_in[14];
    const float* b_out  = (const float*)d_in[15];
    float* out = (float*)d_out;

    float* d_off  = nullptr; cudaGetSymbolAddress((void**)&d_off,  g_off);
    float* d_attn = nullptr; cudaGetSymbolAddress((void**)&d_attn, g_attn);
    float* d_samp = nullptr; cudaGetSymbolAddress((void**)&d_samp, g_samp);

    // ---- flow composition (tiny, sequential) ----
    flow_init_kernel<<<(HW_ + 255) / 256, 256>>>(ff, fb);
    auto slot = [](int i, int j) { return ((i * 5 + j) * 2) * HW_; };
    const int FB = (HW_ + 255) / 256;
    flow_warp_kernel<<<FB, 256>>>(slot(0, 1), slot(1, 2), slot(0, 2));  // f02
    flow_warp_kernel<<<FB, 256>>>(slot(0, 2), slot(2, 3), slot(0, 3));  // f03
    flow_warp_kernel<<<FB, 256>>>(slot(0, 3), slot(3, 4), slot(0, 4));  // f04
    flow_warp_kernel<<<FB, 256>>>(slot(1, 2), slot(2, 3), slot(1, 3));  // f13
    flow_warp_kernel<<<FB, 256>>>(slot(1, 3), slot(3, 4), slot(1, 4));  // f14
    flow_warp_kernel<<<FB, 256>>>(slot(2, 3), slot(3, 4), slot(2, 4));  // f24
    flow_warp_kernel<<<FB, 256>>>(slot(2, 1), slot(1, 0), slot(2, 0));  // b20
    flow_warp_kernel<<<FB, 256>>>(slot(3, 2), slot(2, 1), slot(3, 1));  // b31
    flow_warp_kernel<<<FB, 256>>>(slot(3, 1), slot(1, 0), slot(3, 0));  // b30

    // ---- convs ----
    dim3 cblk(128);
    conv3x3_kernel<1><<<dim3(3, 4, T_ * (256 / 8)), cblk>>>(input_flatten, w_val, b_val, nullptr, 256);
    conv3x3_kernel<0><<<dim3(3, 4, T_ * (320 / 8)), cblk>>>(query, w_off, b_off, d_off, 320);
    conv3x3_kernel<0><<<dim3(3, 4, T_ * (160 / 8)), cblk>>>(query, w_attn, b_attn, d_attn, 160);

    // ---- deformable attention sampling ----
    sample_kernel<<<(T_ * HW_ * HEADS_) / 8, 256>>>(ref_pts);

    // ---- output projection ----
    conv3x3_kernel<0><<<dim3(3, 4, T_ * (256 / 8)), cblk>>>(d_samp, w_out, b_out, out, 256);
}

// round 2
// speedup vs baseline: 1.3340x; 1.3340x over previous
#include <cuda_runtime.h>
#include <cstdint>
#include <math.h>

#define T_ 5
#define H_ 64
#define W_ 96
#define HW_ (H_ * W_)
#define CIN_ 256
#define HEADS_ 8
#define LVLS_ 5
#define PTS_ 4

typedef unsigned long long u64;

// packed fp32x2 helpers (Blackwell FFMA2 — only reachable via PTX)
__device__ __forceinline__ u64 pk2(float lo, float hi) {
    u64 r; asm("mov.b64 %0, {%1, %2};" : "=l"(r) : "f"(lo), "f"(hi)); return r;
}
__device__ __forceinline__ void upk2(u64 v, float& lo, float& hi) {
    asm("mov.b64 {%0, %1}, %2;" : "=f"(lo), "=f"(hi) : "l"(v));
}
__device__ __forceinline__ void ffma2(u64& d, u64 a, u64 b) {
    asm("fma.rn.f32x2 %0, %1, %2, %0;" : "+l"(d) : "l"(a), "l"(b));
}

// ---------------- scratch (static device globals; no allocation) ----------------
__device__ float g_value[(size_t)T_ * HEADS_ * HW_ * 32];   // [t][head][y][x][dh]
__device__ float g_off  [(size_t)T_ * 320 * HW_];           // [t][c][y][x]
__device__ float g_attn [(size_t)T_ * 160 * HW_];           // [t][c][y][x]
__device__ float g_adds [(size_t)4 * 5 * 2 * HW_];          // [i(0..3)][j][c][y][x]
__device__ float g_samp [(size_t)T_ * 256 * HW_];           // [t][c][y][x]

// ---------------- direct 3x3 conv, pad=1, stride=1, packed f32x2 ----------------
// Block: 128 threads. Tile: 32 rows x 32 cols of pixels, 8 output channels.
// Each thread: 2 rows x 4 cols x 8 co = 64 outputs held as 32 packed accumulators.
// LAYOUT 0: out[((t*Cout+co)*H + y)*W + x]
// LAYOUT 1: g_value[(((t*8+head)*HW + y*W + x) << 5) + dh], co = head*32+dh
template <int LAYOUT>
__global__ void __launch_bounds__(128) conv3x3_kernel(
    const float* __restrict__ in, const float* __restrict__ wgt,
    const float* __restrict__ bias, float* __restrict__ out, int Cout)
{
    const int co_blocks = Cout >> 3;
    const int t   = blockIdx.z / co_blocks;
    const int co0 = (blockIdx.z % co_blocks) << 3;
    const int gy0 = blockIdx.y << 5;
    const int gx0 = blockIdx.x << 5;
    const int tid = threadIdx.x;
    const int ty  = tid >> 3;          // 0..15 -> output rows 2ty, 2ty+1
    const int tx  = (tid & 7) << 2;    // 0,4,...,28

    __shared__ float s_in[34 * 34];
    __shared__ __align__(16) float s_w2[8 * 9 * 2];   // weights duplicated: LDS.64 = packed pair

    const float* in_t = in + (size_t)t * CIN_ * HW_;

    u64 acc[8][2][2];                  // [co][row][pair]  (pair0 = px0,1 / pair1 = px2,3)
#pragma unroll
    for (int k = 0; k < 8; k++)
#pragma unroll
        for (int r = 0; r < 2; r++) { acc[k][r][0] = 0ull; acc[k][r][1] = 0ull; }

    for (int ci = 0; ci < CIN_; ci++) {
        const float* img = in_t + (size_t)ci * HW_;
        for (int i = tid; i < 34 * 34; i += 128) {
            int r = i / 34, c = i - r * 34;
            int gy = gy0 - 1 + r, gx = gx0 - 1 + c;
            float v = 0.f;
            if ((unsigned)gy < H_ && (unsigned)gx < W_) v = img[gy * W_ + gx];
            s_in[i] = v;
        }
        if (tid < 72) {
            float w = wgt[((size_t)(co0 + tid / 9) * CIN_ + ci) * 9 + (tid % 9)];
            s_w2[tid * 2] = w; s_w2[tid * 2 + 1] = w;
        }
        __syncthreads();

        // build per-row packed input pairs: P[r][j] = {s[tx+j], s[tx+j+1]}, j=0..4
        u64 P[4][5];
#pragma unroll
        for (int r = 0; r < 4; r++) {
            const float* row = &s_in[(2 * ty + r) * 34 + tx];
            float a0 = row[0], a1 = row[1], a2 = row[2], a3 = row[3], a4 = row[4], a5 = row[5];
            P[r][0] = pk2(a0, a1); P[r][1] = pk2(a1, a2); P[r][2] = pk2(a2, a3);
            P[r][3] = pk2(a3, a4); P[r][4] = pk2(a4, a5);
        }

#pragma unroll
        for (int k = 0; k < 8; k++) {
            const u64* wp = (const u64*)&s_w2[k * 18];
            u64 w[9];
#pragma unroll
            for (int e = 0; e < 9; e++) w[e] = wp[e];
#pragma unroll
            for (int pr = 0; pr < 2; pr++) {
#pragma unroll
                for (int wr = 0; wr < 3; wr++) {
                    const u64* Pr = P[pr + wr];
#pragma unroll
                    for (int wc = 0; wc < 3; wc++) {
                        ffma2(acc[k][pr][0], w[wr * 3 + wc], Pr[wc]);
                        ffma2(acc[k][pr][1], w[wr * 3 + wc], Pr[wc + 2]);
                    }
                }
            }
        }
        __syncthreads();
    }

#pragma unroll
    for (int k = 0; k < 8; k++) {
        const int co = co0 + k;
        const float b = bias[co];
#pragma unroll
        for (int pr = 0; pr < 2; pr++) {
            const int gy = gy0 + 2 * ty + pr;
            float v[4];
            upk2(acc[k][pr][0], v[0], v[1]);
            upk2(acc[k][pr][1], v[2], v[3]);
#pragma unroll
            for (int p = 0; p < 4; p++) {
                const int gx = gx0 + tx + p;
                const float o = v[p] + b;
                if (LAYOUT == 0) {
                    out[((size_t)(t * Cout + co) * H_ + gy) * W_ + gx] = o;
                } else {
                    const int head = co >> 5, dh = co & 31;
                    g_value[(((size_t)(t * 8 + head) * HW_ + gy * W_ + gx) << 5) + dh] = o;
                }
            }
        }
    }
}

// ---------------- flow composition ----------------
__global__ void flow_init_kernel(const float* __restrict__ ff, const float* __restrict__ fb)
{
    int p = blockIdx.x * blockDim.x + threadIdx.x;
    if (p >= HW_) return;
#pragma unroll
    for (int i = 0; i < 4; i++)
#pragma unroll
        for (int j = 0; j < 5; j++) {
            g_adds[((i * 5 + j) * 2 + 0) * HW_ + p] = 0.f;
            g_adds[((i * 5 + j) * 2 + 1) * HW_ + p] = 0.f;
        }
#pragma unroll
    for (int k = 0; k < 4; k++) {
        g_adds[((k * 5 + (k + 1)) * 2 + 0) * HW_ + p] = ff[(k * 2 + 0) * HW_ + p];
        g_adds[((k * 5 + (k + 1)) * 2 + 1) * HW_ + p] = ff[(k * 2 + 1) * HW_ + p];
    }
#pragma unroll
    for (int k = 0; k < 3; k++) {
        g_adds[(((k + 1) * 5 + k) * 2 + 0) * HW_ + p] = fb[(k * 2 + 0) * HW_ + p];
        g_adds[(((k + 1) * 5 + k) * 2 + 1) * HW_ + p] = fb[(k * 2 + 1) * HW_ + p];
    }
}

// dst = base + bilinear_zero_sample(tgt, grid + base)
__global__ void flow_warp_kernel(int base_off, int tgt_off, int dst_off)
{
    int p = blockIdx.x * blockDim.x + threadIdx.x;
    if (p >= HW_) return;
    int y = p / W_, x = p - y * W_;
    const float* base = g_adds + base_off;
    const float* tgt  = g_adds + tgt_off;
    float fx = base[p], fy = base[HW_ + p];
    float px = (float)x + fx, py = (float)y + fy;
    float x0f = floorf(px), y0f = floorf(py);
    int   x0 = (int)x0f, y0 = (int)y0f;
    float wx1 = px - x0f, wx0 = 1.f - wx1;
    float wy1 = py - y0f, wy0 = 1.f - wy1;
    float s0 = 0.f, s1 = 0.f;
    const int xs[4] = {x0, x0 + 1, x0, x0 + 1};
    const int ys[4] = {y0, y0, y0 + 1, y0 + 1};
    const float ws[4] = {wx0 * wy0, wx1 * wy0, wx0 * wy1, wx1 * wy1};
#pragma unroll
    for (int k = 0; k < 4; k++) {
        if ((unsigned)xs[k] < W_ && (unsigned)ys[k] < H_) {
            int idx = ys[k] * W_ + xs[k];
            s0 = fmaf(tgt[idx], ws[k], s0);
            s1 = fmaf(tgt[HW_ + idx], ws[k], s1);
        }
    }
    g_adds[dst_off + p]        = fx + s0;
    g_adds[dst_off + HW_ + p]  = fy + s1;
}

// ---------------- deformable sampling + softmax attention ----------------
__global__ void __launch_bounds__(256) sample_kernel(const float* __restrict__ ref_pts)
{
    const int item = blockIdx.x * 8 + (threadIdx.x >> 5);
    const int lane = threadIdx.x & 31;
    const int head = item & 7;
    const int q    = item >> 3;
    const int t    = q / HW_;
    const int p    = q - t * HW_;
    const int ri   = (t == 4) ? 3 : t;   // reference builds adds row 4 identical to row 3

    const float* attn_base = g_attn + (size_t)t * 160 * HW_ + (size_t)head * 20 * HW_ + p;
    float lg[20];
    float mx = -1e30f;
#pragma unroll
    for (int i = 0; i < 20; i++) { lg[i] = attn_base[(size_t)i * HW_]; mx = fmaxf(mx, lg[i]); }
    float ssum = 0.f;
#pragma unroll
    for (int i = 0; i < 20; i++) { lg[i] = __expf(lg[i] - mx); ssum += lg[i]; }
    const float inv = 1.f / ssum;

    const float* off_base = g_off + (size_t)t * 320 * HW_ + p;
    float out = 0.f;
#pragma unroll
    for (int l = 0; l < LVLS_; l++) {
        const float ax = g_adds[((ri * 5 + l) * 2 + 0) * HW_ + p];
        const float ay = g_adds[((ri * 5 + l) * 2 + 1) * HW_ + p];
        const float rx = ref_pts[((size_t)q * 5 + l) * 2 + 0];
        const float ry = ref_pts[((size_t)q * 5 + l) * 2 + 1];
        const float* vimg = g_value + ((size_t)(l * 8 + head) * HW_ << 5) + lane;
#pragma unroll
        for (int pt = 0; pt < PTS_; pt++) {
            const int ch = ((head * 5 + l) * 4 + pt) * 2;
            const float ox = off_base[(size_t)ch * HW_] + ax;
            const float oy = off_base[(size_t)(ch + 1) * HW_] + ay;
            const float px = fmaf(rx, (float)W_, ox) - 0.5f;
            const float py = fmaf(ry, (float)H_, oy) - 0.5f;
            const float x0f = floorf(px), y0f = floorf(py);
            const int   x0 = (int)x0f, y0 = (int)y0f;
            const float wx1 = px - x0f, wx0 = 1.f - wx1;
            const float wy1 = py - y0f, wy0 = 1.f - wy1;
            float s = 0.f;
            const bool vx0 = (unsigned)x0 < W_,        vx1 = (unsigned)(x0 + 1) < W_;
            const bool vy0 = (unsigned)y0 < H_,        vy1 = (unsigned)(y0 + 1) < H_;
            if (vy0) {
                const long long r0 = (long long)y0 * W_;
                if (vx0) s = fmaf(vimg[(r0 + x0) << 5],     wx0 * wy0, s);
                if (vx1) s = fmaf(vimg[(r0 + x0 + 1) << 5], wx1 * wy0, s);
            }
            if (vy1) {
                const long long r1 = (long long)(y0 + 1) * W_;
                if (vx0) s = fmaf(vimg[(r1 + x0) << 5],     wx0 * wy1, s);
                if (vx1) s = fmaf(vimg[(r1 + x0 + 1) << 5], wx1 * wy1, s);
            }
            out = fmaf(s, lg[l * 4 + pt] * inv, out);
        }
    }
    g_samp[((size_t)t * 256 + (head << 5) + lane) * HW_ + p] = out;
}

// ---------------- launch ----------------
extern "C" void kernel_launch(void* const* d_in, const int* in_sizes, int n_in,
                              void* d_out, int out_size)
{
    (void)in_sizes; (void)n_in; (void)out_size;
    const float* query         = (const float*)d_in[0];
    const float* input_flatten = (const float*)d_in[1];
    const float* ref_pts       = (const float*)d_in[2];
    const float* ff     = (const float*)d_in[6];
    const float* fb     = (const float*)d_in[7];
    const float* w_off  = (const float*)d_in[8];
    const float* b_off  = (const float*)d_in[9];
    const float* w_attn = (const float*)d_in[10];
    const float* b_attn = (const float*)d_in[11];
    const float* w_val  = (const float*)d_in[12];
    const float* b_val  = (const float*)d_in[13];
    const float* w_out  = (const float*)d_in[14];
    const float* b_out  = (const float*)d_in[15];
    float* out = (float*)d_out;

    float* d_off  = nullptr; cudaGetSymbolAddress((void**)&d_off,  g_off);
    float* d_attn = nullptr; cudaGetSymbolAddress((void**)&d_attn, g_attn);
    float* d_samp = nullptr; cudaGetSymbolAddress((void**)&d_samp, g_samp);

    // ---- flow composition (tiny, sequential) ----
    flow_init_kernel<<<(HW_ + 255) / 256, 256>>>(ff, fb);
    auto slot = [](int i, int j) { return ((i * 5 + j) * 2) * HW_; };
    const int FB = (HW_ + 255) / 256;
    flow_warp_kernel<<<FB, 256>>>(slot(0, 1), slot(1, 2), slot(0, 2));  // f02
    flow_warp_kernel<<<FB, 256>>>(slot(0, 2), slot(2, 3), slot(0, 3));  // f03
    flow_warp_kernel<<<FB, 256>>>(slot(0, 3), slot(3, 4), slot(0, 4));  // f04
    flow_warp_kernel<<<FB, 256>>>(slot(1, 2), slot(2, 3), slot(1, 3));  // f13
    flow_warp_kernel<<<FB, 256>>>(slot(1, 3), slot(3, 4), slot(1, 4));  // f14
    flow_warp_kernel<<<FB, 256>>>(slot(2, 3), slot(3, 4), slot(2, 4));  // f24
    flow_warp_kernel<<<FB, 256>>>(slot(2, 1), slot(1, 0), slot(2, 0));  // b20
    flow_warp_kernel<<<FB, 256>>>(slot(3, 2), slot(2, 1), slot(3, 1));  // b31
    flow_warp_kernel<<<FB, 256>>>(slot(3, 1), slot(1, 0), slot(3, 0));  // b30

    // ---- convs (32x32 px tile, 8 co per block) ----
    dim3 cblk(128);
    conv3x3_kernel<1><<<dim3(3, 2, T_ * (256 / 8)), cblk>>>(input_flatten, w_val, b_val, nullptr, 256);
    conv3x3_kernel<0><<<dim3(3, 2, T_ * (320 / 8)), cblk>>>(query, w_off, b_off, d_off, 320);
    conv3x3_kernel<0><<<dim3(3, 2, T_ * (160 / 8)), cblk>>>(query, w_attn, b_attn, d_attn, 160);

    // ---- deformable attention sampling ----
    sample_kernel<<<(T_ * HW_ * HEADS_) / 8, 256>>>(ref_pts);

    // ---- output projection ----
    conv3x3_kernel<0><<<dim3(3, 2, T_ * (256 / 8)), cblk>>>(d_samp, w_out, b_out, out, 256);
}

// round 5
// speedup vs baseline: 3.2897x; 2.4661x over previous
#include <cuda_runtime.h>
#include <cuda_bf16.h>
#include <cstdint>
#include <math.h>

#define T_ 5
#define H_ 64
#define W_ 96
#define HW_ (H_ * W_)
#define HEADS_ 8
#define LVLS_ 5
#define PTS_ 4
#define NPIX_ (T_ * HW_)
#define PW_ (W_ + 2)            // 98
#define PH_ (H_ + 2)            // 66
#define PPIX_ (PW_ * PH_)       // 6468

// ================= helpers =================
__device__ __forceinline__ uint32_t smem_u32(const void* p) {
    uint32_t a;
    asm("{ .reg .u64 t; cvta.to.shared.u64 t, %1; cvt.u32.u64 %0, t; }" : "=r"(a) : "l"(p));
    return a;
}
__device__ __forceinline__ void ldsm4(uint32_t* r, uint32_t addr) {
    asm volatile("ldmatrix.sync.aligned.m8n8.x4.shared.b16 {%0,%1,%2,%3}, [%4];"
        : "=r"(r[0]), "=r"(r[1]), "=r"(r[2]), "=r"(r[3]) : "r"(addr));
}
__device__ __forceinline__ void mma16816(float* c, const uint32_t* a, uint32_t b0, uint32_t b1) {
    asm volatile(
        "mma.sync.aligned.m16n8k16.row.col.f32.bf16.bf16.f32 "
        "{%0,%1,%2,%3}, {%4,%5,%6,%7}, {%8,%9}, {%0,%1,%2,%3};"
        : "+f"(c[0]), "+f"(c[1]), "+f"(c[2]), "+f"(c[3])
        : "r"(a[0]), "r"(a[1]), "r"(a[2]), "r"(a[3]), "r"(b0), "r"(b1));
}

// ================= scratch =================
// padded pixel-major bf16 hi/lo inputs: [t][ppix][256]
__device__ __align__(16) __nv_bfloat16 g_xfh[(size_t)T_ * PPIX_ * 256], g_xfl[(size_t)T_ * PPIX_ * 256];
__device__ __align__(16) __nv_bfloat16 g_xqh[(size_t)T_ * PPIX_ * 256], g_xql[(size_t)T_ * PPIX_ * 256];
__device__ __align__(16) __nv_bfloat16 g_xsh[(size_t)T_ * PPIX_ * 256], g_xsl[(size_t)T_ * PPIX_ * 256];
// weights [shift][CoPad][256] bf16 hi/lo
__device__ __align__(16) __nv_bfloat16 g_wvh[9 * 256 * 256], g_wvl[9 * 256 * 256];
__device__ __align__(16) __nv_bfloat16 g_wph[9 * 512 * 256], g_wpl[9 * 512 * 256];   // off+attn fused
__device__ __align__(16) __nv_bfloat16 g_wuh[9 * 256 * 256], g_wul[9 * 256 * 256];
__device__ float g_value[(size_t)T_ * HEADS_ * HW_ * 32];   // [t][head][pix][dh]
__device__ float g_off  [(size_t)T_ * 320 * HW_];
__device__ float g_attn [(size_t)T_ * 160 * HW_];
__device__ float g_adds [(size_t)4 * 5 * 2 * HW_];

// ================= border zeroing of padded buffers (ALL 256 channels) =================
__global__ void zero_border_kernel()
{
    int idx = blockIdx.x * 256 + threadIdx.x;          // [t][ppix][c32]
    if (idx >= T_ * PPIX_ * 32) return;
    int c32 = idx & 31;
    int pp  = (idx >> 5) % PPIX_;
    int t   = idx / (PPIX_ * 32);
    int py = pp / PW_, px = pp - py * PW_;
    if (py == 0 || py == PH_ - 1 || px == 0 || px == PW_ - 1) {
        size_t o = ((size_t)t * PPIX_ + pp) * 256 + c32 * 8;
        uint4 z = make_uint4(0, 0, 0, 0);
        *(uint4*)((char*)g_xfh + o * 2) = z; *(uint4*)((char*)g_xfl + o * 2) = z;
        *(uint4*)((char*)g_xqh + o * 2) = z; *(uint4*)((char*)g_xql + o * 2) = z;
        *(uint4*)((char*)g_xsh + o * 2) = z; *(uint4*)((char*)g_xsl + o * 2) = z;
    }
}

// ================= input transpose + bf16 hi/lo split (interior) =================
// src [t][256][HW] fp32 -> dst [t][(y+1)*98+(x+1)][256] bf16 (hi, lo)
__global__ void __launch_bounds__(128) prep_x_kernel(
    const float* __restrict__ src, __nv_bfloat16* __restrict__ dh, __nv_bfloat16* __restrict__ dl)
{
    const int y = blockIdx.x, t = blockIdx.y, tid = threadIdx.x;
    __shared__ float s[64][97];
    for (int cib = 0; cib < 4; cib++) {
        __syncthreads();
        for (int i = tid; i < 64 * 96; i += 128) {
            int r = i / 96, c = i - r * 96;
            s[r][c] = src[((size_t)(t * 256 + cib * 64 + r)) * HW_ + y * 96 + c];
        }
        __syncthreads();
        if (tid < 96) {
            size_t ob = ((size_t)t * PPIX_ + (size_t)(y + 1) * PW_ + tid + 1) * 256 + cib * 64;
#pragma unroll 8
            for (int ci = 0; ci < 64; ci++) {
                float v = s[ci][tid];
                __nv_bfloat16 h = __float2bfloat16(v);
                dh[ob + ci] = h;
                dl[ob + ci] = __float2bfloat16(v - __bfloat162float(h));
            }
        }
    }
}

// weights [co][256][3][3] fp32 (x2 sources) -> [shift][CoPad][256] bf16 hi/lo
__global__ void prep_w_kernel(const float* __restrict__ w1, int C1,
                              const float* __restrict__ w2, int C2, int CoPad,
                              __nv_bfloat16* __restrict__ dh, __nv_bfloat16* __restrict__ dl)
{
    int idx = blockIdx.x * 256 + threadIdx.x;
    if (idx >= CoPad * 256 * 9) return;
    int ci = idx & 255, t2 = idx >> 8;
    int co = t2 % CoPad, shift = t2 / CoPad;
    float v = 0.f;
    if (co < C1)            v = w1[((size_t)co * 256 + ci) * 9 + shift];
    else if (co < C1 + C2)  v = w2[((size_t)(co - C1) * 256 + ci) * 9 + shift];
    __nv_bfloat16 h = __float2bfloat16(v);
    dh[idx] = h;
    dl[idx] = __float2bfloat16(v - __bfloat162float(h));
}

// ================= HMMA implicit-GEMM 3x3 conv =================
// CTA: 128 co x 256 pix, 512 threads (16 warps: warp_m = wid&3, warp_n = wid>>2).
// Warp tile: 32 co x 64 pix. K: 4 ci-chunks(64) x 9 shifts x 4 k16 x 3 split terms.
// B tile: 464 padded rows x 128B (covers 256 pixels + row-wrap + +-99 halo shifts).
// layout 0: out[t][Cout][pix]; 1: g_value; 2: off(0..319)+attn(320..479).
#define BROWS  464
#define BBYTES (BROWS * 128)            // 59392
#define BH_OFF 0
#define BL_OFF BBYTES                   // 59392
#define AH_OFF (2 * BBYTES)             // 118784
#define AL_OFF (2 * BBYTES + 16384)     // 135168
#define SMTOT  (2 * BBYTES + 32768)     // 151552

__global__ void __launch_bounds__(512, 1) hmma_conv_kernel(
    const __nv_bfloat16* __restrict__ wh, const __nv_bfloat16* __restrict__ wl,
    const __nv_bfloat16* __restrict__ xh, const __nv_bfloat16* __restrict__ xl,
    const float* __restrict__ bias1, const float* __restrict__ bias2,
    float* __restrict__ out, int Cout1, int CoPad, int layout)
{
    extern __shared__ char smem[];
    const uint32_t sb = smem_u32(smem);
    const int tid = threadIdx.x, wid = tid >> 5, lane = tid & 31;
    const int warp_m = wid & 3, warp_n = wid >> 2;
    const int t = blockIdx.z, o0 = blockIdx.y << 8, co0 = blockIdx.x << 7;
    const int pmin = o0 + 2 * (o0 / 96);

    float C[2][8][4];
#pragma unroll
    for (int m = 0; m < 2; m++)
#pragma unroll
        for (int n = 0; n < 8; n++)
#pragma unroll
            for (int k = 0; k < 4; k++) C[m][n][k] = 0.f;

    // per-lane ldmatrix row indices
    const int kh_b = (lane >> 3) & 1;
    const int kh_a = lane >> 4;
    int prow[4];
#pragma unroll
    for (int j = 0; j < 4; j++) {
        int nl = warp_n * 64 + j * 16 + ((lane >> 4) << 3) + (lane & 7);
        int o = o0 + nl;
        prow[j] = o + 2 * (o / 96) + 99 - pmin;     // 99..360; +off in [0, 460)
    }
    int arow[2];
#pragma unroll
    for (int m = 0; m < 2; m++) arow[m] = warp_m * 32 + m * 16 + (lane & 15);

    for (int chunk = 0; chunk < 4; chunk++) {
        __syncthreads();
        // load B tiles (BROWS rows x 128B each, hi+lo), zero OOB rows
        {
            const int prem = PPIX_ - pmin;   // rows available in gmem for this t
            const size_t gb = (((size_t)t * PPIX_ + pmin) * 256 + chunk * 64) * 2;
#pragma unroll
            for (int i = 0; i < 8; i++) {
                int idx = tid + i * 512;
                if (idx < BROWS * 8) {
                    int r = idx >> 3, c = idx & 7;
                    uint32_t dof = r * 128 + ((c ^ (r & 7)) << 4);
                    uint4 vh = make_uint4(0, 0, 0, 0), vl = make_uint4(0, 0, 0, 0);
                    if (r < prem) {
                        vh = *(const uint4*)((const char*)xh + gb + (size_t)r * 512 + c * 16);
                        vl = *(const uint4*)((const char*)xl + gb + (size_t)r * 512 + c * 16);
                    }
                    *(uint4*)(smem + BH_OFF + dof) = vh;
                    *(uint4*)(smem + BL_OFF + dof) = vl;
                }
            }
        }
        for (int shift = 0; shift < 9; shift++) {
            __syncthreads();   // protect A from previous consumers
            {
#pragma unroll
                for (int i = 0; i < 2; i++) {
                    int idx = tid + i * 512;
                    int r = idx >> 3, c = idx & 7;
                    size_t gsrc = (((size_t)(shift * CoPad + co0 + r)) * 256 + chunk * 64) * 2 + c * 16;
                    uint32_t dof = r * 128 + ((c ^ (r & 7)) << 4);
                    *(uint4*)(smem + AH_OFF + dof) = *(const uint4*)((const char*)wh + gsrc);
                    *(uint4*)(smem + AL_OFF + dof) = *(const uint4*)((const char*)wl + gsrc);
                }
            }
            __syncthreads();
            const int off = (shift / 3 - 1) * PW_ + (shift % 3 - 1);
#pragma unroll
            for (int ks = 0; ks < 4; ks++) {
                uint32_t a[2][4], b[4][4];
                // A hi
#pragma unroll
                for (int m = 0; m < 2; m++) {
                    int c = ks * 2 + kh_a;
                    ldsm4(a[m], sb + AH_OFF + arow[m] * 128 + ((c ^ (arow[m] & 7)) << 4));
                }
                // B lo -> term: Ah*Bl
#pragma unroll
                for (int j = 0; j < 4; j++) {
                    int r = prow[j] + off;
                    int c = ks * 2 + kh_b;
                    ldsm4(b[j], sb + BL_OFF + r * 128 + ((c ^ (r & 7)) << 4));
                }
#pragma unroll
                for (int m = 0; m < 2; m++)
#pragma unroll
                    for (int n = 0; n < 8; n++)
                        mma16816(C[m][n], a[m], b[n >> 1][(n & 1) * 2], b[n >> 1][(n & 1) * 2 + 1]);
                // B hi -> term: Ah*Bh
#pragma unroll
                for (int j = 0; j < 4; j++) {
                    int r = prow[j] + off;
                    int c = ks * 2 + kh_b;
                    ldsm4(b[j], sb + BH_OFF + r * 128 + ((c ^ (r & 7)) << 4));
                }
#pragma unroll
                for (int m = 0; m < 2; m++)
#pragma unroll
                    for (int n = 0; n < 8; n++)
                        mma16816(C[m][n], a[m], b[n >> 1][(n & 1) * 2], b[n >> 1][(n & 1) * 2 + 1]);
                // A lo -> term: Al*Bh
#pragma unroll
                for (int m = 0; m < 2; m++) {
                    int c = ks * 2 + kh_a;
                    ldsm4(a[m], sb + AL_OFF + arow[m] * 128 + ((c ^ (arow[m] & 7)) << 4));
                }
#pragma unroll
                for (int m = 0; m < 2; m++)
#pragma unroll
                    for (int n = 0; n < 8; n++)
                        mma16816(C[m][n], a[m], b[n >> 1][(n & 1) * 2], b[n >> 1][(n & 1) * 2 + 1]);
            }
        }
    }

    // epilogue
#pragma unroll
    for (int m = 0; m < 2; m++) {
        const int coA = co0 + warp_m * 32 + m * 16 + (lane >> 2);
#pragma unroll
        for (int n = 0; n < 8; n++) {
            const int px = o0 + warp_n * 64 + n * 8 + ((lane & 3) << 1);
#pragma unroll
            for (int half = 0; half < 2; half++) {
                const int co = coA + half * 8;
                const float v0 = C[m][n][half * 2 + 0];
                const float v1 = C[m][n][half * 2 + 1];
                if (layout == 0) {
                    const float bv = bias1[co];
                    float* op = out + ((size_t)t * Cout1 + co) * HW_ + px;
                    op[0] = v0 + bv; op[1] = v1 + bv;
                } else if (layout == 1) {
                    const float bv = bias1[co];
                    const int head = co >> 5, dh = co & 31;
                    float* op = g_value + (((size_t)(t * 8 + head) * HW_ + px) << 5) + dh;
                    op[0]  = v0 + bv;
                    op[32] = v1 + bv;
                } else {
                    if (co < 480) {
                        float bv; float* op;
                        if (co < 320) { bv = bias1[co];       op = g_off  + ((size_t)t * 320 + co)       * HW_ + px; }
                        else          { bv = bias2[co - 320]; op = g_attn + ((size_t)t * 160 + co - 320) * HW_ + px; }
                        op[0] = v0 + bv; op[1] = v1 + bv;
                    }
                }
            }
        }
    }
}

// ================= flow composition =================
__global__ void flow_init_kernel(const float* __restrict__ ff, const float* __restrict__ fb)
{
    int p = blockIdx.x * blockDim.x + threadIdx.x;
    if (p >= HW_) return;
#pragma unroll
    for (int i = 0; i < 4; i++)
#pragma unroll
        for (int j = 0; j < 5; j++) {
            g_adds[((i * 5 + j) * 2 + 0) * HW_ + p] = 0.f;
            g_adds[((i * 5 + j) * 2 + 1) * HW_ + p] = 0.f;
        }
#pragma unroll
    for (int k = 0; k < 4; k++) {
        g_adds[((k * 5 + (k + 1)) * 2 + 0) * HW_ + p] = ff[(k * 2 + 0) * HW_ + p];
        g_adds[((k * 5 + (k + 1)) * 2 + 1) * HW_ + p] = ff[(k * 2 + 1) * HW_ + p];
    }
#pragma unroll
    for (int k = 0; k < 3; k++) {
        g_adds[(((k + 1) * 5 + k) * 2 + 0) * HW_ + p] = fb[(k * 2 + 0) * HW_ + p];
        g_adds[(((k + 1) * 5 + k) * 2 + 1) * HW_ + p] = fb[(k * 2 + 1) * HW_ + p];
    }
}

__global__ void flow_warp_kernel(int base_off, int tgt_off, int dst_off)
{
    int p = blockIdx.x * blockDim.x + threadIdx.x;
    if (p >= HW_) return;
    int y = p / W_, x = p - y * W_;
    const float* bptr = g_adds + base_off;
    const float* tgt  = g_adds + tgt_off;
    float fx = bptr[p], fy = bptr[HW_ + p];
    float px = (float)x + fx, py = (float)y + fy;
    float x0f = floorf(px), y0f = floorf(py);
    int   x0 = (int)x0f, y0 = (int)y0f;
    float wx1 = px - x0f, wx0 = 1.f - wx1;
    float wy1 = py - y0f, wy0 = 1.f - wy1;
    float s0 = 0.f, s1 = 0.f;
    const int xs[4] = {x0, x0 + 1, x0, x0 + 1};
    const int ys[4] = {y0, y0, y0 + 1, y0 + 1};
    const float ws[4] = {wx0 * wy0, wx1 * wy0, wx0 * wy1, wx1 * wy1};
#pragma unroll
    for (int k = 0; k < 4; k++) {
        if ((unsigned)xs[k] < W_ && (unsigned)ys[k] < H_) {
            int idx = ys[k] * W_ + xs[k];
            s0 = fmaf(tgt[idx], ws[k], s0);
            s1 = fmaf(tgt[HW_ + idx], ws[k], s1);
        }
    }
    g_adds[dst_off + p]       = fx + s0;
    g_adds[dst_off + HW_ + p] = fy + s1;
}

// ================= deformable sampling =================
__global__ void __launch_bounds__(256) sample_kernel(const float* __restrict__ ref_pts)
{
    const int item = blockIdx.x * 8 + (threadIdx.x >> 5);
    const int lane = threadIdx.x & 31;
    const int head = item & 7;
    const int q    = item >> 3;
    const int t    = q / HW_;
    const int p    = q - t * HW_;
    const int ri   = (t == 4) ? 3 : t;

    const float* attn_base = g_attn + (size_t)t * 160 * HW_ + (size_t)head * 20 * HW_ + p;
    float lg[20];
    float mx = -1e30f;
#pragma unroll
    for (int i = 0; i < 20; i++) { lg[i] = attn_base[(size_t)i * HW_]; mx = fmaxf(mx, lg[i]); }
    float ssum = 0.f;
#pragma unroll
    for (int i = 0; i < 20; i++) { lg[i] = __expf(lg[i] - mx); ssum += lg[i]; }
    const float inv = 1.f / ssum;

    const float* off_base = g_off + (size_t)t * 320 * HW_ + p;
    float outv = 0.f;
#pragma unroll
    for (int l = 0; l < LVLS_; l++) {
        const float ax = g_adds[((ri * 5 + l) * 2 + 0) * HW_ + p];
        const float ay = g_adds[((ri * 5 + l) * 2 + 1) * HW_ + p];
        const float rx = ref_pts[((size_t)q * 5 + l) * 2 + 0];
        const float ry = ref_pts[((size_t)q * 5 + l) * 2 + 1];
        const float* vimg = g_value + ((size_t)(l * 8 + head) * HW_ << 5) + lane;
#pragma unroll
        for (int pt = 0; pt < PTS_; pt++) {
            const int ch = ((head * 5 + l) * 4 + pt) * 2;
            const float ox = off_base[(size_t)ch * HW_] + ax;
            const float oy = off_base[(size_t)(ch + 1) * HW_] + ay;
            const float px = fmaf(rx, (float)W_, ox) - 0.5f;
            const float py = fmaf(ry, (float)H_, oy) - 0.5f;
            const float x0f = floorf(px), y0f = floorf(py);
            const int   x0 = (int)x0f, y0 = (int)y0f;
            const float wx1 = px - x0f, wx0 = 1.f - wx1;
            const float wy1 = py - y0f, wy0 = 1.f - wy1;
            float s = 0.f;
            const bool vx0 = (unsigned)x0 < W_,       vx1 = (unsigned)(x0 + 1) < W_;
            const bool vy0 = (unsigned)y0 < H_,       vy1 = (unsigned)(y0 + 1) < H_;
            if (vy0) {
                const long long r0 = (long long)y0 * W_;
                if (vx0) s = fmaf(vimg[(r0 + x0) << 5],     wx0 * wy0, s);
                if (vx1) s = fmaf(vimg[(r0 + x0 + 1) << 5], wx1 * wy0, s);
            }
            if (vy1) {
                const long long r1 = (long long)(y0 + 1) * W_;
                if (vx0) s = fmaf(vimg[(r1 + x0) << 5],     wx0 * wy1, s);
                if (vx1) s = fmaf(vimg[(r1 + x0 + 1) << 5], wx1 * wy1, s);
            }
            outv = fmaf(s, lg[l * 4 + pt] * inv, outv);
        }
    }
    const int y = p / 96, x = p - y * 96;
    const size_t ob = ((size_t)t * PPIX_ + (size_t)(y + 1) * PW_ + x + 1) * 256 + (head << 5) + lane;
    __nv_bfloat16 h = __float2bfloat16(outv);
    g_xsh[ob] = h;
    g_xsl[ob] = __float2bfloat16(outv - __bfloat162float(h));
}

// ================= launch =================
extern "C" void kernel_launch(void* const* d_in, const int* in_sizes, int n_in,
                              void* d_out, int out_size)
{
    (void)in_sizes; (void)n_in; (void)out_size;
    const float* query         = (const float*)d_in[0];
    const float* input_flatten = (const float*)d_in[1];
    const float* ref_pts       = (const float*)d_in[2];
    const float* ff     = (const float*)d_in[6];
    const float* fb     = (const float*)d_in[7];
    const float* w_off  = (const float*)d_in[8];
    const float* b_off  = (const float*)d_in[9];
    const float* w_attn = (const float*)d_in[10];
    const float* b_attn = (const float*)d_in[11];
    const float* w_val  = (const float*)d_in[12];
    const float* b_val  = (const float*)d_in[13];
    const float* w_out  = (const float*)d_in[14];
    const float* b_out  = (const float*)d_in[15];
    float* out = (float*)d_out;

    cudaFuncSetAttribute(hmma_conv_kernel, cudaFuncAttributeMaxDynamicSharedMemorySize, SMTOT);

    __nv_bfloat16 *xfh, *xfl, *xqh, *xql, *xsh, *xsl;
    __nv_bfloat16 *wvh, *wvl, *wph, *wpl, *wuh, *wul;
    cudaGetSymbolAddress((void**)&xfh, g_xfh); cudaGetSymbolAddress((void**)&xfl, g_xfl);
    cudaGetSymbolAddress((void**)&xqh, g_xqh); cudaGetSymbolAddress((void**)&xql, g_xql);
    cudaGetSymbolAddress((void**)&xsh, g_xsh); cudaGetSymbolAddress((void**)&xsl, g_xsl);
    cudaGetSymbolAddress((void**)&wvh, g_wvh); cudaGetSymbolAddress((void**)&wvl, g_wvl);
    cudaGetSymbolAddress((void**)&wph, g_wph); cudaGetSymbolAddress((void**)&wpl, g_wpl);
    cudaGetSymbolAddress((void**)&wuh, g_wuh); cudaGetSymbolAddress((void**)&wul, g_wul);

    // ---- preps ----
    zero_border_kernel<<<(T_ * PPIX_ * 32 + 255) / 256, 256>>>();
    prep_x_kernel<<<dim3(64, 5), 128>>>(input_flatten, xfh, xfl);
    prep_x_kernel<<<dim3(64, 5), 128>>>(query, xqh, xql);
    prep_w_kernel<<<(256 * 256 * 9 + 255) / 256, 256>>>(w_val, 256, nullptr, 0, 256, wvh, wvl);
    prep_w_kernel<<<(512 * 256 * 9 + 255) / 256, 256>>>(w_off, 320, w_attn, 160, 512, wph, wpl);
    prep_w_kernel<<<(256 * 256 * 9 + 255) / 256, 256>>>(w_out, 256, nullptr, 0, 256, wuh, wul);

    // ---- flow composition ----
    flow_init_kernel<<<(HW_ + 255) / 256, 256>>>(ff, fb);
    auto slot = [](int i, int j) { return ((i * 5 + j) * 2) * HW_; };
    const int FB = (HW_ + 255) / 256;
    flow_warp_kernel<<<FB, 256>>>(slot(0, 1), slot(1, 2), slot(0, 2));
    flow_warp_kernel<<<FB, 256>>>(slot(0, 2), slot(2, 3), slot(0, 3));
    flow_warp_kernel<<<FB, 256>>>(slot(0, 3), slot(3, 4), slot(0, 4));
    flow_warp_kernel<<<FB, 256>>>(slot(1, 2), slot(2, 3), slot(1, 3));
    flow_warp_kernel<<<FB, 256>>>(slot(1, 3), slot(3, 4), slot(1, 4));
    flow_warp_kernel<<<FB, 256>>>(slot(2, 3), slot(3, 4), slot(2, 4));
    flow_warp_kernel<<<FB, 256>>>(slot(2, 1), slot(1, 0), slot(2, 0));
    flow_warp_kernel<<<FB, 256>>>(slot(3, 2), slot(2, 1), slot(3, 1));
    flow_warp_kernel<<<FB, 256>>>(slot(3, 1), slot(1, 0), slot(3, 0));

    // ---- HMMA convs ----
    hmma_conv_kernel<<<dim3(2, 24, 5), 512, SMTOT>>>(wvh, wvl, xfh, xfl, b_val, nullptr, nullptr, 256, 256, 1);
    hmma_conv_kernel<<<dim3(4, 24, 5), 512, SMTOT>>>(wph, wpl, xqh, xql, b_off, b_attn, nullptr, 320, 512, 2);

    // ---- deformable attention sampling ----
    sample_kernel<<<(T_ * HW_ * HEADS_) / 8, 256>>>(ref_pts);

    // ---- output projection ----
    hmma_conv_kernel<<<dim3(2, 24, 5), 512, SMTOT>>>(wuh, wul, xsh, xsl, b_out, nullptr, out, 256, 256, 0);
}